// round 6
// baseline (speedup 1.0000x reference)
#include <cuda_runtime.h>
#include <cuda_bf16.h>
#include <cstdint>
#include <math.h>

#define BB 4
#define SS 2048
#define EE 768
#define NH 12
#define MTOK (BB*SS)      /* 8192 */
#define QKVN (3*EE)       /* 2304 */

// ---------------- scratch (static device arrays; no allocation) -------------
__device__ __align__(256) __nv_bfloat16 g_qkvhi[(size_t)MTOK * QKVN];
__device__ __align__(256) __nv_bfloat16 g_qkvlo[(size_t)MTOK * QKVN];
__device__ __align__(256) __nv_bfloat16 g_xhi [(size_t)MTOK * EE];
__device__ __align__(256) __nv_bfloat16 g_xlo [(size_t)MTOK * EE];
__device__ __align__(256) __nv_bfloat16 g_wahi[(size_t)QKVN * EE];
__device__ __align__(256) __nv_bfloat16 g_walo[(size_t)QKVN * EE];
__device__ __align__(256) __nv_bfloat16 g_wphi[(size_t)EE * EE];
__device__ __align__(256) __nv_bfloat16 g_wplo[(size_t)EE * EE];
__device__ __align__(256) __nv_bfloat16 g_ahi [(size_t)MTOK * EE];
__device__ __align__(256) __nv_bfloat16 g_alo [(size_t)MTOK * EE];

// ---------------- PTX helpers ----------------------------------------------
__device__ __forceinline__ uint32_t smem_u32(const void* p) {
    uint32_t a;
    asm("{ .reg .u64 t; cvta.to.shared.u64 t, %1; cvt.u32.u64 %0, t; }"
        : "=r"(a) : "l"(p));
    return a;
}
#define CP_ASYNC16(sa, g) \
    asm volatile("cp.async.cg.shared.global [%0], [%1], 16;" :: "r"(sa), "l"(g) : "memory")
#define CP_COMMIT() asm volatile("cp.async.commit_group;" ::: "memory")
#define CP_WAIT(n)  asm volatile("cp.async.wait_group %0;" :: "n"(n) : "memory")

__device__ __forceinline__ void ldsm4(uint32_t& r0, uint32_t& r1,
                                      uint32_t& r2, uint32_t& r3, uint32_t a) {
    asm volatile("ldmatrix.sync.aligned.m8n8.x4.shared.b16 {%0,%1,%2,%3}, [%4];"
                 : "=r"(r0), "=r"(r1), "=r"(r2), "=r"(r3) : "r"(a));
}
__device__ __forceinline__ void ldsm4t(uint32_t& r0, uint32_t& r1,
                                       uint32_t& r2, uint32_t& r3, uint32_t a) {
    asm volatile("ldmatrix.sync.aligned.m8n8.x4.trans.shared.b16 {%0,%1,%2,%3}, [%4];"
                 : "=r"(r0), "=r"(r1), "=r"(r2), "=r"(r3) : "r"(a));
}
__device__ __forceinline__ void mma16816(float* c, const uint32_t* a,
                                         const uint32_t* b) {
    asm volatile("mma.sync.aligned.m16n8k16.row.col.f32.bf16.bf16.f32 "
                 "{%0,%1,%2,%3}, {%4,%5,%6,%7}, {%8,%9}, {%0,%1,%2,%3};"
                 : "+f"(c[0]), "+f"(c[1]), "+f"(c[2]), "+f"(c[3])
                 : "r"(a[0]), "r"(a[1]), "r"(a[2]), "r"(a[3]),
                   "r"(b[0]), "r"(b[1]));
}
__device__ __forceinline__ uint32_t packbf(float a, float b) {
    uint32_t r;
    asm("cvt.rn.bf16x2.f32 %0, %1, %2;" : "=r"(r) : "f"(b), "f"(a));
    return r;
}
__device__ __forceinline__ float bfround(float v) {
    return __bfloat162float(__float2bfloat16(v));
}
// SW128 swizzle over 128B rows (attention tiles)
__device__ __forceinline__ uint32_t sw_addr(uint32_t base, int row, int chunk) {
    uint32_t off = (uint32_t)(row * 128 + chunk * 16);
    return base + (off ^ ((off >> 3) & 0x70));
}
// SW64 swizzle over 64B rows (gemm tiles)
__device__ __forceinline__ uint32_t sw64_addr(uint32_t base, int row, int chunk) {
    uint32_t off = (uint32_t)(row * 64 + chunk * 16);
    return base + (off ^ ((off >> 2) & 0x30));
}

// ---------------- hi/lo converts --------------------------------------------
__global__ void __launch_bounds__(256) convert_hilo_kernel(
    const float* __restrict__ s, __nv_bfloat16* __restrict__ hi,
    __nv_bfloat16* __restrict__ lo, int n)
{
    int i = blockIdx.x * 256 + threadIdx.x;
    if (i < n) {
        float v = s[i];
        __nv_bfloat16 h = __float2bfloat16(v);
        hi[i] = h;
        lo[i] = __float2bfloat16(v - __bfloat162float(h));
    }
}

__global__ void __launch_bounds__(256) transpose_hilo_kernel(
    const float* __restrict__ W, __nv_bfloat16* __restrict__ Thi,
    __nv_bfloat16* __restrict__ Tlo, int K, int N)   // W[K][N] -> T[N][K]
{
    __shared__ float t[32][33];
    int n0 = blockIdx.x * 32, k0 = blockIdx.y * 32;
    int tx = threadIdx.x, ty = threadIdx.y;
    #pragma unroll
    for (int i = 0; i < 32; i += 8)
        t[ty + i][tx] = W[(size_t)(k0 + ty + i) * N + n0 + tx];
    __syncthreads();
    #pragma unroll
    for (int i = 0; i < 32; i += 8) {
        float v = t[tx][ty + i];
        __nv_bfloat16 h = __float2bfloat16(v);
        size_t o = (size_t)(n0 + ty + i) * K + k0 + tx;
        Thi[o] = h;
        Tlo[o] = __float2bfloat16(v - __bfloat162float(h));
    }
}

// ---------------- HMMA 3-term bf16 GEMM ------------------------------------
// CTA 128x256, 8 warps (2M x 4N), warp tile 64x64. KC=32.
// stage: Ah 8K | Al 8K | Bh 16K | Bl 16K = 48KB; 3 stages = 144KB.
#define G3_STAGE   49152
#define G3_STAGES  3
#define G3_SMEM    (G3_STAGES * G3_STAGE)

__device__ __forceinline__ void g3_load_chunk(
    uint32_t sbase, const __nv_bfloat16* Ahi, const __nv_bfloat16* Alo,
    const __nv_bfloat16* Bhi, const __nv_bfloat16* Blo,
    int row0, int col0, int K, int c, int tid)
{
    const __nv_bfloat16* ah = Ahi + (size_t)row0 * K + c * 32;
    const __nv_bfloat16* al = Alo + (size_t)row0 * K + c * 32;
    const __nv_bfloat16* bh = Bhi + (size_t)col0 * K + c * 32;
    const __nv_bfloat16* bl = Blo + (size_t)col0 * K + c * 32;
    #pragma unroll
    for (int i = 0; i < 2; i++) {               // A: 128 rows x 4 chunks
        int idx = tid + i * 256;
        int r = idx >> 2, cb = idx & 3;
        CP_ASYNC16(sw64_addr(sbase, r, cb), (const void*)(ah + (size_t)r * K + cb * 8));
        CP_ASYNC16(sw64_addr(sbase + 8192, r, cb), (const void*)(al + (size_t)r * K + cb * 8));
    }
    #pragma unroll
    for (int i = 0; i < 4; i++) {               // B: 256 rows x 4 chunks
        int idx = tid + i * 256;
        int r = idx >> 2, cb = idx & 3;
        CP_ASYNC16(sw64_addr(sbase + 16384, r, cb), (const void*)(bh + (size_t)r * K + cb * 8));
        CP_ASYNC16(sw64_addr(sbase + 32768, r, cb), (const void*)(bl + (size_t)r * K + cb * 8));
    }
    CP_COMMIT();
}

__global__ void __launch_bounds__(256, 1) gemm3_kernel(
    const __nv_bfloat16* __restrict__ Ahi, const __nv_bfloat16* __restrict__ Alo,
    const __nv_bfloat16* __restrict__ Bhi, const __nv_bfloat16* __restrict__ Blo,
    const float* __restrict__ bias, float* __restrict__ Cf,
    __nv_bfloat16* __restrict__ Chi, __nv_bfloat16* __restrict__ Clo,
    int M, int N, int K)
{
    extern __shared__ __align__(1024) char smg[];
    uint32_t sb = smem_u32(smg);
    const int tid = threadIdx.x;
    const int wid = tid >> 5, lid = tid & 31;
    const int wm = (wid >> 2) * 64;      // warp row offset (2 row-groups)
    const int wn = (wid & 3) * 64;       // warp col offset (4 col-groups)
    const int lrow = lid & 15;
    const int lck  = lid >> 4;
    const int row0 = blockIdx.y * 128, col0 = blockIdx.x * 256;
    const int nch = K / 32;

    float acc[4][8][4];
    #pragma unroll
    for (int mi = 0; mi < 4; mi++)
        #pragma unroll
        for (int nj = 0; nj < 8; nj++)
            #pragma unroll
            for (int r = 0; r < 4; r++) acc[mi][nj][r] = 0.0f;

    g3_load_chunk(sb,               Ahi, Alo, Bhi, Blo, row0, col0, K, 0, tid);
    g3_load_chunk(sb + G3_STAGE,    Ahi, Alo, Bhi, Blo, row0, col0, K, 1, tid);
    g3_load_chunk(sb + 2*G3_STAGE,  Ahi, Alo, Bhi, Blo, row0, col0, K, 2, tid);

    for (int c = 0; c < nch; c++) {
        CP_WAIT(2);
        __syncthreads();
        uint32_t st = sb + (uint32_t)(c % G3_STAGES) * G3_STAGE;
        uint32_t bAh = st, bAl = st + 8192, bBh = st + 16384, bBl = st + 32768;

        #pragma unroll
        for (int step = 0; step < 2; step++) {
            int kc = 2 * step;
            uint32_t ah[4][4], al[4][4];
            #pragma unroll
            for (int mi = 0; mi < 4; mi++) {
                ldsm4(ah[mi][0], ah[mi][1], ah[mi][2], ah[mi][3],
                      sw64_addr(bAh, wm + mi * 16 + lrow, kc + lck));
                ldsm4(al[mi][0], al[mi][1], al[mi][2], al[mi][3],
                      sw64_addr(bAl, wm + mi * 16 + lrow, kc + lck));
            }
            #pragma unroll
            for (int g = 0; g < 4; g++) {        // 16-col B groups
                uint32_t bh[2][2], bl[2][2], r0, r1, r2, r3;
                ldsm4(r0, r1, r2, r3, sw64_addr(bBh, wn + g * 16 + lrow, kc + lck));
                bh[0][0] = r0; bh[1][0] = r1; bh[0][1] = r2; bh[1][1] = r3;
                ldsm4(r0, r1, r2, r3, sw64_addr(bBl, wn + g * 16 + lrow, kc + lck));
                bl[0][0] = r0; bl[1][0] = r1; bl[0][1] = r2; bl[1][1] = r3;
                // 3 terms, 8 independent accumulators between same-acc reuse
                #pragma unroll
                for (int mi = 0; mi < 4; mi++)
                    #pragma unroll
                    for (int u = 0; u < 2; u++)
                        mma16816(acc[mi][2 * g + u], ah[mi], bh[u]);
                #pragma unroll
                for (int mi = 0; mi < 4; mi++)
                    #pragma unroll
                    for (int u = 0; u < 2; u++)
                        mma16816(acc[mi][2 * g + u], ah[mi], bl[u]);
                #pragma unroll
                for (int mi = 0; mi < 4; mi++)
                    #pragma unroll
                    for (int u = 0; u < 2; u++)
                        mma16816(acc[mi][2 * g + u], al[mi], bh[u]);
            }
        }
        __syncthreads();
        if (c + G3_STAGES < nch)
            g3_load_chunk(st, Ahi, Alo, Bhi, Blo, row0, col0, K, c + G3_STAGES, tid);
    }

    const int gID = lid >> 2, tig = lid & 3;
    #pragma unroll
    for (int mi = 0; mi < 4; mi++) {
        int r = row0 + wm + mi * 16 + gID;
        #pragma unroll
        for (int nj = 0; nj < 8; nj++) {
            int cc = col0 + wn + nj * 8 + tig * 2;
            float b0 = bias[cc], b1 = bias[cc + 1];
            float v0 = acc[mi][nj][0] + b0, v1 = acc[mi][nj][1] + b1;
            float v2 = acc[mi][nj][2] + b0, v3 = acc[mi][nj][3] + b1;
            if (Cf) {
                *(float2*)&Cf[(size_t)r * N + cc] = make_float2(v0, v1);
                *(float2*)&Cf[(size_t)(r + 8) * N + cc] = make_float2(v2, v3);
            } else {
                *(uint32_t*)&Chi[(size_t)r * N + cc] = packbf(v0, v1);
                *(uint32_t*)&Clo[(size_t)r * N + cc] =
                    packbf(v0 - bfround(v0), v1 - bfround(v1));
                *(uint32_t*)&Chi[(size_t)(r + 8) * N + cc] = packbf(v2, v3);
                *(uint32_t*)&Clo[(size_t)(r + 8) * N + cc] =
                    packbf(v2 - bfround(v2), v3 - bfround(v3));
            }
        }
    }
}

// ---------------- HMMA causal flash attention -------------------------------
// CTA: 128 q-rows x 1 head. 8 warps x 16 rows. Bc=64 keys, double-buffered.
#define ATT_SMEM 98304

__device__ __forceinline__ void att_load_kv(
    uint32_t stbase, const __nv_bfloat16* qkvhi, const __nv_bfloat16* qkvlo,
    size_t tokbase, int kcol, int vcol, int kt, int tid)
{
    const __nv_bfloat16* srcs[4];
    srcs[0] = qkvhi + (tokbase + kt * 64) * QKVN + kcol;
    srcs[1] = qkvlo + (tokbase + kt * 64) * QKVN + kcol;
    srcs[2] = qkvhi + (tokbase + kt * 64) * QKVN + vcol;
    srcs[3] = qkvlo + (tokbase + kt * 64) * QKVN + vcol;
    #pragma unroll
    for (int t = 0; t < 4; t++) {
        uint32_t tb = stbase + t * 8192;
        #pragma unroll
        for (int i = 0; i < 2; i++) {
            int idx = tid + i * 256;
            int r = idx >> 3, cb = idx & 7;
            CP_ASYNC16(sw_addr(tb, r, cb), (const void*)(srcs[t] + (size_t)r * QKVN + cb * 8));
        }
    }
    CP_COMMIT();
}

__global__ void __launch_bounds__(256) attn_hmma_kernel(
    const __nv_bfloat16* __restrict__ qkvhi, const __nv_bfloat16* __restrict__ qkvlo,
    __nv_bfloat16* __restrict__ ohi, __nv_bfloat16* __restrict__ olo)
{
    extern __shared__ __align__(1024) char sma[];
    uint32_t sb = smem_u32(sma);
    const int tid = threadIdx.x, wid = tid >> 5, lid = tid & 31;
    const int lrow = lid & 15, lck = lid >> 4, gID = lid >> 2, tig = lid & 3;
    const int wm = wid * 16;
    const int bh = blockIdx.x;
    const int b = bh / NH, h = bh % NH;
    const int qt = gridDim.y - 1 - blockIdx.y;     // long tiles first
    const int q0 = qt * 128;
    const size_t tokbase = (size_t)b * SS;
    const int qcol = h * 64, kcol = EE + h * 64, vcol = 2 * EE + h * 64;
    const int ntiles = 2 * qt + 2;

    const uint32_t sQh = sb, sQl = sb + 16384;

    {
        const __nv_bfloat16* qh = qkvhi + (tokbase + q0) * QKVN + qcol;
        const __nv_bfloat16* ql = qkvlo + (tokbase + q0) * QKVN + qcol;
        #pragma unroll
        for (int i = 0; i < 4; i++) {
            int idx = tid + i * 256;
            int r = idx >> 3, cb = idx & 7;
            CP_ASYNC16(sw_addr(sQh, r, cb), (const void*)(qh + (size_t)r * QKVN + cb * 8));
            CP_ASYNC16(sw_addr(sQl, r, cb), (const void*)(ql + (size_t)r * QKVN + cb * 8));
        }
    }
    att_load_kv(sb + 32768, qkvhi, qkvlo, tokbase, kcol, vcol, 0, tid);
    att_load_kv(sb + 32768 + 32768, qkvhi, qkvlo, tokbase, kcol, vcol, 1, tid);

    float m0 = -1e30f, m1 = -1e30f, l0 = 0.0f, l1 = 0.0f;
    float of[8][4];
    #pragma unroll
    for (int j = 0; j < 8; j++)
        #pragma unroll
        for (int e = 0; e < 4; e++) of[j][e] = 0.0f;

    uint32_t qh[4][4], ql[4][4];
    bool qloaded = false;

    for (int kt = 0; kt < ntiles; kt++) {
        if (kt + 1 < ntiles) { CP_WAIT(1); } else { CP_WAIT(0); }
        __syncthreads();
        if (!qloaded) {
            #pragma unroll
            for (int ks = 0; ks < 4; ks++) {
                ldsm4(qh[ks][0], qh[ks][1], qh[ks][2], qh[ks][3],
                      sw_addr(sQh, wm + lrow, 2 * ks + lck));
                ldsm4(ql[ks][0], ql[ks][1], ql[ks][2], ql[ks][3],
                      sw_addr(sQl, wm + lrow, 2 * ks + lck));
            }
            qloaded = true;
        }
        const uint32_t st = sb + 32768 + (uint32_t)(kt & 1) * 32768;
        const bool active = (kt * 64 <= q0 + wm + 15);

        if (active) {
            float sf[8][4];
            #pragma unroll
            for (int j = 0; j < 8; j++)
                #pragma unroll
                for (int e = 0; e < 4; e++) sf[j][e] = 0.0f;
            #pragma unroll
            for (int ks = 0; ks < 4; ks++) {
                #pragma unroll
                for (int g = 0; g < 4; g++) {
                    uint32_t kh[2][2], kl[2][2], r0, r1, r2, r3;
                    ldsm4(r0, r1, r2, r3, sw_addr(st, g * 16 + lrow, 2 * ks + lck));
                    kh[0][0] = r0; kh[1][0] = r1; kh[0][1] = r2; kh[1][1] = r3;
                    ldsm4(r0, r1, r2, r3, sw_addr(st + 8192, g * 16 + lrow, 2 * ks + lck));
                    kl[0][0] = r0; kl[1][0] = r1; kl[0][1] = r2; kl[1][1] = r3;
                    #pragma unroll
                    for (int u = 0; u < 2; u++) {
                        mma16816(sf[2 * g + u], qh[ks], kh[u]);
                        mma16816(sf[2 * g + u], qh[ks], kl[u]);
                        mma16816(sf[2 * g + u], ql[ks], kh[u]);
                    }
                }
            }

            const bool masked = (kt * 64 + 63 > q0 + wm);
            #pragma unroll
            for (int j = 0; j < 8; j++) {
                #pragma unroll
                for (int e = 0; e < 4; e++) {
                    float v = sf[j][e] * 0.125f;
                    if (masked) {
                        int c = kt * 64 + 8 * j + tig * 2 + (e & 1);
                        int r = q0 + wm + gID + (e >> 1) * 8;
                        if (c > r) v = -1e30f;
                    }
                    sf[j][e] = v;
                }
            }

            float mt0 = -1e30f, mt1 = -1e30f;
            #pragma unroll
            for (int j = 0; j < 8; j++) {
                mt0 = fmaxf(mt0, fmaxf(sf[j][0], sf[j][1]));
                mt1 = fmaxf(mt1, fmaxf(sf[j][2], sf[j][3]));
            }
            mt0 = fmaxf(mt0, __shfl_xor_sync(0xffffffffu, mt0, 1));
            mt0 = fmaxf(mt0, __shfl_xor_sync(0xffffffffu, mt0, 2));
            mt1 = fmaxf(mt1, __shfl_xor_sync(0xffffffffu, mt1, 1));
            mt1 = fmaxf(mt1, __shfl_xor_sync(0xffffffffu, mt1, 2));
            float mn0 = fmaxf(m0, mt0), mn1 = fmaxf(m1, mt1);
            float a0 = __expf(m0 - mn0), a1 = __expf(m1 - mn1);
            m0 = mn0; m1 = mn1;

            float sum0 = 0.0f, sum1 = 0.0f;
            uint32_t ph[4][4], pl[4][4];
            #pragma unroll
            for (int j = 0; j < 8; j++) {
                float p0 = __expf(sf[j][0] - mn0), p1 = __expf(sf[j][1] - mn0);
                float p2 = __expf(sf[j][2] - mn1), p3 = __expf(sf[j][3] - mn1);
                sum0 += p0 + p1; sum1 += p2 + p3;
                int ks = j >> 1, half = (j & 1) * 2;
                ph[ks][half + 0] = packbf(p0, p1);
                ph[ks][half + 1] = packbf(p2, p3);
                pl[ks][half + 0] = packbf(p0 - bfround(p0), p1 - bfround(p1));
                pl[ks][half + 1] = packbf(p2 - bfround(p2), p3 - bfround(p3));
            }
            sum0 += __shfl_xor_sync(0xffffffffu, sum0, 1);
            sum0 += __shfl_xor_sync(0xffffffffu, sum0, 2);
            sum1 += __shfl_xor_sync(0xffffffffu, sum1, 1);
            sum1 += __shfl_xor_sync(0xffffffffu, sum1, 2);
            l0 = l0 * a0 + sum0; l1 = l1 * a1 + sum1;
            #pragma unroll
            for (int j = 0; j < 8; j++) {
                of[j][0] *= a0; of[j][1] *= a0; of[j][2] *= a1; of[j][3] *= a1;
            }

            const uint32_t sVh = st + 16384, sVl = st + 24576;
            #pragma unroll
            for (int ks = 0; ks < 4; ks++) {
                #pragma unroll
                for (int dg = 0; dg < 4; dg++) {
                    uint32_t vh[2][2], vl[2][2], r0, r1, r2, r3;
                    ldsm4t(r0, r1, r2, r3, sw_addr(sVh, ks * 16 + lrow, 2 * dg + lck));
                    vh[0][0] = r0; vh[0][1] = r1; vh[1][0] = r2; vh[1][1] = r3;
                    ldsm4t(r0, r1, r2, r3, sw_addr(sVl, ks * 16 + lrow, 2 * dg + lck));
                    vl[0][0] = r0; vl[0][1] = r1; vl[1][0] = r2; vl[1][1] = r3;
                    #pragma unroll
                    for (int u = 0; u < 2; u++) {
                        mma16816(of[2 * dg + u], ph[ks], vh[u]);
                        mma16816(of[2 * dg + u], ph[ks], vl[u]);
                        mma16816(of[2 * dg + u], pl[ks], vh[u]);
                    }
                }
            }
        }

        __syncthreads();
        if (kt + 2 < ntiles)
            att_load_kv(sb + 32768 + (uint32_t)(kt & 1) * 32768,
                        qkvhi, qkvlo, tokbase, kcol, vcol, kt + 2, tid);
    }

    float inv0 = 1.0f / l0, inv1 = 1.0f / l1;
    size_t row0 = (tokbase + q0 + wm + gID) * EE;
    size_t row1 = (tokbase + q0 + wm + gID + 8) * EE;
    #pragma unroll
    for (int j = 0; j < 8; j++) {
        int d = h * 64 + 8 * j + tig * 2;
        float v0 = of[j][0] * inv0, v1 = of[j][1] * inv0;
        float v2 = of[j][2] * inv1, v3 = of[j][3] * inv1;
        *(uint32_t*)&ohi[row0 + d] = packbf(v0, v1);
        *(uint32_t*)&olo[row0 + d] = packbf(v0 - bfround(v0), v1 - bfround(v1));
        *(uint32_t*)&ohi[row1 + d] = packbf(v2, v3);
        *(uint32_t*)&olo[row1 + d] = packbf(v2 - bfround(v2), v3 - bfround(v3));
    }
}

// ---------------------------------------------------------------------------
extern "C" void kernel_launch(void* const* d_in, const int* in_sizes, int n_in,
                              void* d_out, int out_size)
{
    (void)in_sizes; (void)n_in; (void)out_size;
    const float* x      = (const float*)d_in[0];
    // d_in[1] = mask — strict-upper-triangular causal mask, applied analytically
    const float* W_attn = (const float*)d_in[2];
    const float* b_attn = (const float*)d_in[3];
    const float* W_proj = (const float*)d_in[4];
    const float* b_proj = (const float*)d_in[5];
    float* out = (float*)d_out;

    __nv_bfloat16 *qhi, *qlo, *xhi, *xlo, *wahi, *walo, *wphi, *wplo, *ahi, *alo;
    cudaGetSymbolAddress((void**)&qhi,  g_qkvhi);
    cudaGetSymbolAddress((void**)&qlo,  g_qkvlo);
    cudaGetSymbolAddress((void**)&xhi,  g_xhi);
    cudaGetSymbolAddress((void**)&xlo,  g_xlo);
    cudaGetSymbolAddress((void**)&wahi, g_wahi);
    cudaGetSymbolAddress((void**)&walo, g_walo);
    cudaGetSymbolAddress((void**)&wphi, g_wphi);
    cudaGetSymbolAddress((void**)&wplo, g_wplo);
    cudaGetSymbolAddress((void**)&ahi,  g_ahi);
    cudaGetSymbolAddress((void**)&alo,  g_alo);

    cudaFuncSetAttribute(gemm3_kernel,
                         cudaFuncAttributeMaxDynamicSharedMemorySize, G3_SMEM);
    cudaFuncSetAttribute(attn_hmma_kernel,
                         cudaFuncAttributeMaxDynamicSharedMemorySize, ATT_SMEM);

    {
        int n = MTOK * EE;
        convert_hilo_kernel<<<(n + 255) / 256, 256>>>(x, xhi, xlo, n);
        transpose_hilo_kernel<<<dim3(QKVN / 32, EE / 32), dim3(32, 8)>>>(
            W_attn, wahi, walo, EE, QKVN);
        transpose_hilo_kernel<<<dim3(EE / 32, EE / 32), dim3(32, 8)>>>(
            W_proj, wphi, wplo, EE, EE);
    }
    gemm3_kernel<<<dim3(QKVN / 256, MTOK / 128), 256, G3_SMEM>>>(
        xhi, xlo, wahi, walo, b_attn, nullptr, qhi, qlo, MTOK, QKVN, EE);
    attn_hmma_kernel<<<dim3(BB * NH, SS / 128), 256, ATT_SMEM>>>(qhi, qlo, ahi, alo);
    gemm3_kernel<<<dim3(EE / 256, MTOK / 128), 256, G3_SMEM>>>(
        ahi, alo, wphi, wplo, b_proj, out, nullptr, nullptr, MTOK, EE, EE);
}

// round 7
// speedup vs baseline: 1.1101x; 1.1101x over previous
#include <cuda_runtime.h>
#include <cuda_bf16.h>
#include <cstdint>
#include <math.h>

#define BB 4
#define SS 2048
#define EE 768
#define NH 12
#define MTOK (BB*SS)      /* 8192 */
#define QKVN (3*EE)       /* 2304 */

// ---------------- scratch (static device arrays; no allocation) -------------
__device__ __align__(256) __nv_bfloat16 g_qkvhi[(size_t)MTOK * QKVN];
__device__ __align__(256) __nv_bfloat16 g_qkvlo[(size_t)MTOK * QKVN];
__device__ __align__(256) __nv_bfloat16 g_xhi [(size_t)MTOK * EE];
__device__ __align__(256) __nv_bfloat16 g_xlo [(size_t)MTOK * EE];
__device__ __align__(256) __nv_bfloat16 g_wahi[(size_t)QKVN * EE];
__device__ __align__(256) __nv_bfloat16 g_walo[(size_t)QKVN * EE];
__device__ __align__(256) __nv_bfloat16 g_wphi[(size_t)EE * EE];
__device__ __align__(256) __nv_bfloat16 g_wplo[(size_t)EE * EE];
__device__ __align__(256) __nv_bfloat16 g_ahi [(size_t)MTOK * EE];
__device__ __align__(256) __nv_bfloat16 g_alo [(size_t)MTOK * EE];

// ---------------- PTX helpers ----------------------------------------------
__device__ __forceinline__ uint32_t smem_u32(const void* p) {
    uint32_t a;
    asm("{ .reg .u64 t; cvta.to.shared.u64 t, %1; cvt.u32.u64 %0, t; }"
        : "=r"(a) : "l"(p));
    return a;
}
#define CP_ASYNC16(sa, g) \
    asm volatile("cp.async.cg.shared.global [%0], [%1], 16;" :: "r"(sa), "l"(g) : "memory")
#define CP_COMMIT() asm volatile("cp.async.commit_group;" ::: "memory")
#define CP_WAIT(n)  asm volatile("cp.async.wait_group %0;" :: "n"(n) : "memory")

__device__ __forceinline__ void ldsm4(uint32_t& r0, uint32_t& r1,
                                      uint32_t& r2, uint32_t& r3, uint32_t a) {
    asm volatile("ldmatrix.sync.aligned.m8n8.x4.shared.b16 {%0,%1,%2,%3}, [%4];"
                 : "=r"(r0), "=r"(r1), "=r"(r2), "=r"(r3) : "r"(a));
}
__device__ __forceinline__ void ldsm4t(uint32_t& r0, uint32_t& r1,
                                       uint32_t& r2, uint32_t& r3, uint32_t a) {
    asm volatile("ldmatrix.sync.aligned.m8n8.x4.trans.shared.b16 {%0,%1,%2,%3}, [%4];"
                 : "=r"(r0), "=r"(r1), "=r"(r2), "=r"(r3) : "r"(a));
}
__device__ __forceinline__ void mma16816(float* c, const uint32_t* a,
                                         const uint32_t* b) {
    asm volatile("mma.sync.aligned.m16n8k16.row.col.f32.bf16.bf16.f32 "
                 "{%0,%1,%2,%3}, {%4,%5,%6,%7}, {%8,%9}, {%0,%1,%2,%3};"
                 : "+f"(c[0]), "+f"(c[1]), "+f"(c[2]), "+f"(c[3])
                 : "r"(a[0]), "r"(a[1]), "r"(a[2]), "r"(a[3]),
                   "r"(b[0]), "r"(b[1]));
}
__device__ __forceinline__ uint32_t packbf(float a, float b) {
    uint32_t r;
    asm("cvt.rn.bf16x2.f32 %0, %1, %2;" : "=r"(r) : "f"(b), "f"(a));
    return r;
}
__device__ __forceinline__ float bfround(float v) {
    return __bfloat162float(__float2bfloat16(v));
}
// SW128 swizzle over 128B rows
__device__ __forceinline__ uint32_t sw_addr(uint32_t base, int row, int chunk) {
    uint32_t off = (uint32_t)(row * 128 + chunk * 16);
    return base + (off ^ ((off >> 3) & 0x70));
}

// ---------------- hi/lo converts --------------------------------------------
__global__ void __launch_bounds__(256) convert_hilo_kernel(
    const float* __restrict__ s, __nv_bfloat16* __restrict__ hi,
    __nv_bfloat16* __restrict__ lo, int n)
{
    int i = blockIdx.x * 256 + threadIdx.x;
    if (i < n) {
        float v = s[i];
        __nv_bfloat16 h = __float2bfloat16(v);
        hi[i] = h;
        lo[i] = __float2bfloat16(v - __bfloat162float(h));
    }
}

__global__ void __launch_bounds__(256) transpose_hilo_kernel(
    const float* __restrict__ W, __nv_bfloat16* __restrict__ Thi,
    __nv_bfloat16* __restrict__ Tlo, int K, int N)   // W[K][N] -> T[N][K]
{
    __shared__ float t[32][33];
    int n0 = blockIdx.x * 32, k0 = blockIdx.y * 32;
    int tx = threadIdx.x, ty = threadIdx.y;
    #pragma unroll
    for (int i = 0; i < 32; i += 8)
        t[ty + i][tx] = W[(size_t)(k0 + ty + i) * N + n0 + tx];
    __syncthreads();
    #pragma unroll
    for (int i = 0; i < 32; i += 8) {
        float v = t[tx][ty + i];
        __nv_bfloat16 h = __float2bfloat16(v);
        size_t o = (size_t)(n0 + ty + i) * K + k0 + tx;
        Thi[o] = h;
        Tlo[o] = __float2bfloat16(v - __bfloat162float(h));
    }
}

// ---------------- HMMA 3-term bf16 GEMM ------------------------------------
// CTA 128x128, 8 warps (2M x 4N), warp tile 64x32, KC=64, 3-stage cp.async.
// Inner loop software-pipelined: step s+1 fragments loaded between step s MMAs.
#define G3_STAGE   65536        /* 4 tensors x 16KB */
#define G3_STAGES  3
#define G3_SMEM    (G3_STAGES * G3_STAGE)

struct FragA { uint32_t a[4][4]; };   // 4 m-tiles x 4 regs
struct FragB { uint32_t b[4][2]; };   // 4 n-tiles x 2 regs

__device__ __forceinline__ void load_fragA(FragA& fh, FragA& fl,
                                           uint32_t bAh, uint32_t bAl,
                                           int wm, int lrow, int kcl) {
    #pragma unroll
    for (int mi = 0; mi < 4; mi++) {
        ldsm4(fh.a[mi][0], fh.a[mi][1], fh.a[mi][2], fh.a[mi][3],
              sw_addr(bAh, wm + mi * 16 + lrow, kcl));
        ldsm4(fl.a[mi][0], fl.a[mi][1], fl.a[mi][2], fl.a[mi][3],
              sw_addr(bAl, wm + mi * 16 + lrow, kcl));
    }
}
__device__ __forceinline__ void load_fragB(FragB& fh, FragB& fl,
                                           uint32_t bBh, uint32_t bBl,
                                           int wn, int lrow, int kcl) {
    #pragma unroll
    for (int g = 0; g < 2; g++) {
        uint32_t r0, r1, r2, r3;
        ldsm4(r0, r1, r2, r3, sw_addr(bBh, wn + g * 16 + lrow, kcl));
        fh.b[2*g][0] = r0; fh.b[2*g+1][0] = r1; fh.b[2*g][1] = r2; fh.b[2*g+1][1] = r3;
        ldsm4(r0, r1, r2, r3, sw_addr(bBl, wn + g * 16 + lrow, kcl));
        fl.b[2*g][0] = r0; fl.b[2*g+1][0] = r1; fl.b[2*g][1] = r2; fl.b[2*g+1][1] = r3;
    }
}
__device__ __forceinline__ void mma_term(float acc[4][4][4],
                                         const FragA& A, const FragB& B) {
    #pragma unroll
    for (int mi = 0; mi < 4; mi++)
        #pragma unroll
        for (int nj = 0; nj < 4; nj++)
            mma16816(acc[mi][nj], A.a[mi], B.b[nj]);
}

__device__ __forceinline__ void g3_load_chunk(
    uint32_t sbase, const __nv_bfloat16* Ahi, const __nv_bfloat16* Alo,
    const __nv_bfloat16* Bhi, const __nv_bfloat16* Blo,
    int row0, int col0, int K, int c, int tid)
{
    const __nv_bfloat16* srcs[4];
    srcs[0] = Ahi + (size_t)row0 * K + c * 64;
    srcs[1] = Alo + (size_t)row0 * K + c * 64;
    srcs[2] = Bhi + (size_t)col0 * K + c * 64;
    srcs[3] = Blo + (size_t)col0 * K + c * 64;
    #pragma unroll
    for (int t = 0; t < 4; t++) {
        const __nv_bfloat16* src = srcs[t];
        uint32_t tb = sbase + t * 16384;
        #pragma unroll
        for (int i = 0; i < 4; i++) {
            int idx = tid + i * 256;
            int r = idx >> 3, cb = idx & 7;
            CP_ASYNC16(sw_addr(tb, r, cb), (const void*)(src + (size_t)r * K + cb * 8));
        }
    }
    CP_COMMIT();
}

__global__ void __launch_bounds__(256) gemm3_kernel(
    const __nv_bfloat16* __restrict__ Ahi, const __nv_bfloat16* __restrict__ Alo,
    const __nv_bfloat16* __restrict__ Bhi, const __nv_bfloat16* __restrict__ Blo,
    const float* __restrict__ bias, float* __restrict__ Cf,
    __nv_bfloat16* __restrict__ Chi, __nv_bfloat16* __restrict__ Clo,
    int M, int N, int K)
{
    extern __shared__ __align__(1024) char smg[];
    uint32_t sb = smem_u32(smg);
    const int tid = threadIdx.x;
    const int wid = tid >> 5, lid = tid & 31;
    const int wm = (wid >> 2) * 64;
    const int wn = (wid & 3) * 32;
    const int lrow = lid & 15;
    const int lck  = lid >> 4;
    const int row0 = blockIdx.y * 128, col0 = blockIdx.x * 128;
    const int nch = K / 64;

    float acc[4][4][4];
    #pragma unroll
    for (int mi = 0; mi < 4; mi++)
        #pragma unroll
        for (int nj = 0; nj < 4; nj++)
            #pragma unroll
            for (int r = 0; r < 4; r++) acc[mi][nj][r] = 0.0f;

    g3_load_chunk(sb,               Ahi, Alo, Bhi, Blo, row0, col0, K, 0, tid);
    g3_load_chunk(sb + G3_STAGE,    Ahi, Alo, Bhi, Blo, row0, col0, K, 1, tid);
    g3_load_chunk(sb + 2*G3_STAGE,  Ahi, Alo, Bhi, Blo, row0, col0, K, 2, tid);

    for (int c = 0; c < nch; c++) {
        CP_WAIT(2);
        __syncthreads();
        uint32_t st = sb + (uint32_t)(c % G3_STAGES) * G3_STAGE;
        uint32_t bAh = st, bAl = st + 16384, bBh = st + 32768, bBl = st + 49152;

        FragA a0h, a0l, a1h, a1l;
        FragB b0h, b0l, b1h, b1l;

        // step 0 fragments
        load_fragA(a0h, a0l, bAh, bAl, wm, lrow, 0 + lck);
        load_fragB(b0h, b0l, bBh, bBl, wn, lrow, 0 + lck);
        // ---- step 0 (prefetch step 1 between MMA groups) ----
        load_fragA(a1h, a1l, bAh, bAl, wm, lrow, 2 + lck);
        mma_term(acc, a0h, b0h);
        load_fragB(b1h, b1l, bBh, bBl, wn, lrow, 2 + lck);
        mma_term(acc, a0h, b0l);
        mma_term(acc, a0l, b0h);
        // ---- step 1 (prefetch step 2) ----
        load_fragA(a0h, a0l, bAh, bAl, wm, lrow, 4 + lck);
        mma_term(acc, a1h, b1h);
        load_fragB(b0h, b0l, bBh, bBl, wn, lrow, 4 + lck);
        mma_term(acc, a1h, b1l);
        mma_term(acc, a1l, b1h);
        // ---- step 2 (prefetch step 3) ----
        load_fragA(a1h, a1l, bAh, bAl, wm, lrow, 6 + lck);
        mma_term(acc, a0h, b0h);
        load_fragB(b1h, b1l, bBh, bBl, wn, lrow, 6 + lck);
        mma_term(acc, a0h, b0l);
        mma_term(acc, a0l, b0h);
        // ---- step 3 ----
        mma_term(acc, a1h, b1h);
        mma_term(acc, a1h, b1l);
        mma_term(acc, a1l, b1h);

        __syncthreads();
        if (c + G3_STAGES < nch)
            g3_load_chunk(st, Ahi, Alo, Bhi, Blo, row0, col0, K, c + G3_STAGES, tid);
    }

    const int gID = lid >> 2, tig = lid & 3;
    #pragma unroll
    for (int mi = 0; mi < 4; mi++) {
        int r = row0 + wm + mi * 16 + gID;
        #pragma unroll
        for (int nj = 0; nj < 4; nj++) {
            int cc = col0 + wn + nj * 8 + tig * 2;
            float b0 = bias[cc], b1 = bias[cc + 1];
            float v0 = acc[mi][nj][0] + b0, v1 = acc[mi][nj][1] + b1;
            float v2 = acc[mi][nj][2] + b0, v3 = acc[mi][nj][3] + b1;
            if (Cf) {
                *(float2*)&Cf[(size_t)r * N + cc] = make_float2(v0, v1);
                *(float2*)&Cf[(size_t)(r + 8) * N + cc] = make_float2(v2, v3);
            } else {
                *(uint32_t*)&Chi[(size_t)r * N + cc] = packbf(v0, v1);
                *(uint32_t*)&Clo[(size_t)r * N + cc] =
                    packbf(v0 - bfround(v0), v1 - bfround(v1));
                *(uint32_t*)&Chi[(size_t)(r + 8) * N + cc] = packbf(v2, v3);
                *(uint32_t*)&Clo[(size_t)(r + 8) * N + cc] =
                    packbf(v2 - bfround(v2), v3 - bfround(v3));
            }
        }
    }
}

// ---------------- HMMA causal flash attention -------------------------------
// CTA: 128 q-rows x 1 head. 8 warps x 16 rows. Bc=64 keys, double-buffered.
#define ATT_SMEM 98304

__device__ __forceinline__ void att_load_kv(
    uint32_t stbase, const __nv_bfloat16* qkvhi, const __nv_bfloat16* qkvlo,
    size_t tokbase, int kcol, int vcol, int kt, int tid)
{
    const __nv_bfloat16* srcs[4];
    srcs[0] = qkvhi + (tokbase + kt * 64) * QKVN + kcol;
    srcs[1] = qkvlo + (tokbase + kt * 64) * QKVN + kcol;
    srcs[2] = qkvhi + (tokbase + kt * 64) * QKVN + vcol;
    srcs[3] = qkvlo + (tokbase + kt * 64) * QKVN + vcol;
    #pragma unroll
    for (int t = 0; t < 4; t++) {
        uint32_t tb = stbase + t * 8192;
        #pragma unroll
        for (int i = 0; i < 2; i++) {
            int idx = tid + i * 256;
            int r = idx >> 3, cb = idx & 7;
            CP_ASYNC16(sw_addr(tb, r, cb), (const void*)(srcs[t] + (size_t)r * QKVN + cb * 8));
        }
    }
    CP_COMMIT();
}

__global__ void __launch_bounds__(256) attn_hmma_kernel(
    const __nv_bfloat16* __restrict__ qkvhi, const __nv_bfloat16* __restrict__ qkvlo,
    __nv_bfloat16* __restrict__ ohi, __nv_bfloat16* __restrict__ olo)
{
    extern __shared__ __align__(1024) char sma[];
    uint32_t sb = smem_u32(sma);
    const int tid = threadIdx.x, wid = tid >> 5, lid = tid & 31;
    const int lrow = lid & 15, lck = lid >> 4, gID = lid >> 2, tig = lid & 3;
    const int wm = wid * 16;
    const int bh = blockIdx.x;
    const int b = bh / NH, h = bh % NH;
    const int qt = gridDim.y - 1 - blockIdx.y;     // long tiles first
    const int q0 = qt * 128;
    const size_t tokbase = (size_t)b * SS;
    const int qcol = h * 64, kcol = EE + h * 64, vcol = 2 * EE + h * 64;
    const int ntiles = 2 * qt + 2;

    const uint32_t sQh = sb, sQl = sb + 16384;

    {
        const __nv_bfloat16* qh = qkvhi + (tokbase + q0) * QKVN + qcol;
        const __nv_bfloat16* ql = qkvlo + (tokbase + q0) * QKVN + qcol;
        #pragma unroll
        for (int i = 0; i < 4; i++) {
            int idx = tid + i * 256;
            int r = idx >> 3, cb = idx & 7;
            CP_ASYNC16(sw_addr(sQh, r, cb), (const void*)(qh + (size_t)r * QKVN + cb * 8));
            CP_ASYNC16(sw_addr(sQl, r, cb), (const void*)(ql + (size_t)r * QKVN + cb * 8));
        }
    }
    att_load_kv(sb + 32768, qkvhi, qkvlo, tokbase, kcol, vcol, 0, tid);
    att_load_kv(sb + 32768 + 32768, qkvhi, qkvlo, tokbase, kcol, vcol, 1, tid);

    float m0 = -1e30f, m1 = -1e30f, l0 = 0.0f, l1 = 0.0f;
    float of[8][4];
    #pragma unroll
    for (int j = 0; j < 8; j++)
        #pragma unroll
        for (int e = 0; e < 4; e++) of[j][e] = 0.0f;

    uint32_t qh[4][4], ql[4][4];
    bool qloaded = false;

    for (int kt = 0; kt < ntiles; kt++) {
        if (kt + 1 < ntiles) { CP_WAIT(1); } else { CP_WAIT(0); }
        __syncthreads();
        if (!qloaded) {
            #pragma unroll
            for (int ks = 0; ks < 4; ks++) {
                ldsm4(qh[ks][0], qh[ks][1], qh[ks][2], qh[ks][3],
                      sw_addr(sQh, wm + lrow, 2 * ks + lck));
                ldsm4(ql[ks][0], ql[ks][1], ql[ks][2], ql[ks][3],
                      sw_addr(sQl, wm + lrow, 2 * ks + lck));
            }
            qloaded = true;
        }
        const uint32_t st = sb + 32768 + (uint32_t)(kt & 1) * 32768;
        const bool active = (kt * 64 <= q0 + wm + 15);

        if (active) {
            float sf[8][4];
            #pragma unroll
            for (int j = 0; j < 8; j++)
                #pragma unroll
                for (int e = 0; e < 4; e++) sf[j][e] = 0.0f;
            #pragma unroll
            for (int ks = 0; ks < 4; ks++) {
                #pragma unroll
                for (int g = 0; g < 4; g++) {
                    uint32_t kh[2][2], kl[2][2], r0, r1, r2, r3;
                    ldsm4(r0, r1, r2, r3, sw_addr(st, g * 16 + lrow, 2 * ks + lck));
                    kh[0][0] = r0; kh[1][0] = r1; kh[0][1] = r2; kh[1][1] = r3;
                    ldsm4(r0, r1, r2, r3, sw_addr(st + 8192, g * 16 + lrow, 2 * ks + lck));
                    kl[0][0] = r0; kl[1][0] = r1; kl[0][1] = r2; kl[1][1] = r3;
                    #pragma unroll
                    for (int u = 0; u < 2; u++) {
                        mma16816(sf[2 * g + u], qh[ks], kh[u]);
                        mma16816(sf[2 * g + u], qh[ks], kl[u]);
                        mma16816(sf[2 * g + u], ql[ks], kh[u]);
                    }
                }
            }

            const bool masked = (kt * 64 + 63 > q0 + wm);
            #pragma unroll
            for (int j = 0; j < 8; j++) {
                #pragma unroll
                for (int e = 0; e < 4; e++) {
                    float v = sf[j][e] * 0.125f;
                    if (masked) {
                        int c = kt * 64 + 8 * j + tig * 2 + (e & 1);
                        int r = q0 + wm + gID + (e >> 1) * 8;
                        if (c > r) v = -1e30f;
                    }
                    sf[j][e] = v;
                }
            }

            float mt0 = -1e30f, mt1 = -1e30f;
            #pragma unroll
            for (int j = 0; j < 8; j++) {
                mt0 = fmaxf(mt0, fmaxf(sf[j][0], sf[j][1]));
                mt1 = fmaxf(mt1, fmaxf(sf[j][2], sf[j][3]));
            }
            mt0 = fmaxf(mt0, __shfl_xor_sync(0xffffffffu, mt0, 1));
            mt0 = fmaxf(mt0, __shfl_xor_sync(0xffffffffu, mt0, 2));
            mt1 = fmaxf(mt1, __shfl_xor_sync(0xffffffffu, mt1, 1));
            mt1 = fmaxf(mt1, __shfl_xor_sync(0xffffffffu, mt1, 2));
            float mn0 = fmaxf(m0, mt0), mn1 = fmaxf(m1, mt1);
            float a0 = __expf(m0 - mn0), a1 = __expf(m1 - mn1);
            m0 = mn0; m1 = mn1;

            float sum0 = 0.0f, sum1 = 0.0f;
            uint32_t ph[4][4], pl[4][4];
            #pragma unroll
            for (int j = 0; j < 8; j++) {
                float p0 = __expf(sf[j][0] - mn0), p1 = __expf(sf[j][1] - mn0);
                float p2 = __expf(sf[j][2] - mn1), p3 = __expf(sf[j][3] - mn1);
                sum0 += p0 + p1; sum1 += p2 + p3;
                int ks = j >> 1, half = (j & 1) * 2;
                ph[ks][half + 0] = packbf(p0, p1);
                ph[ks][half + 1] = packbf(p2, p3);
                pl[ks][half + 0] = packbf(p0 - bfround(p0), p1 - bfround(p1));
                pl[ks][half + 1] = packbf(p2 - bfround(p2), p3 - bfround(p3));
            }
            sum0 += __shfl_xor_sync(0xffffffffu, sum0, 1);
            sum0 += __shfl_xor_sync(0xffffffffu, sum0, 2);
            sum1 += __shfl_xor_sync(0xffffffffu, sum1, 1);
            sum1 += __shfl_xor_sync(0xffffffffu, sum1, 2);
            l0 = l0 * a0 + sum0; l1 = l1 * a1 + sum1;
            #pragma unroll
            for (int j = 0; j < 8; j++) {
                of[j][0] *= a0; of[j][1] *= a0; of[j][2] *= a1; of[j][3] *= a1;
            }

            const uint32_t sVh = st + 16384, sVl = st + 24576;
            #pragma unroll
            for (int ks = 0; ks < 4; ks++) {
                #pragma unroll
                for (int dg = 0; dg < 4; dg++) {
                    uint32_t vh[2][2], vl[2][2], r0, r1, r2, r3;
                    ldsm4t(r0, r1, r2, r3, sw_addr(sVh, ks * 16 + lrow, 2 * dg + lck));
                    vh[0][0] = r0; vh[0][1] = r1; vh[1][0] = r2; vh[1][1] = r3;
                    ldsm4t(r0, r1, r2, r3, sw_addr(sVl, ks * 16 + lrow, 2 * dg + lck));
                    vl[0][0] = r0; vl[0][1] = r1; vl[1][0] = r2; vl[1][1] = r3;
                    #pragma unroll
                    for (int u = 0; u < 2; u++) {
                        mma16816(of[2 * dg + u], ph[ks], vh[u]);
                        mma16816(of[2 * dg + u], ph[ks], vl[u]);
                        mma16816(of[2 * dg + u], pl[ks], vh[u]);
                    }
                }
            }
        }

        __syncthreads();
        if (kt + 2 < ntiles)
            att_load_kv(sb + 32768 + (uint32_t)(kt & 1) * 32768,
                        qkvhi, qkvlo, tokbase, kcol, vcol, kt + 2, tid);
    }

    float inv0 = 1.0f / l0, inv1 = 1.0f / l1;
    size_t row0 = (tokbase + q0 + wm + gID) * EE;
    size_t row1 = (tokbase + q0 + wm + gID + 8) * EE;
    #pragma unroll
    for (int j = 0; j < 8; j++) {
        int d = h * 64 + 8 * j + tig * 2;
        float v0 = of[j][0] * inv0, v1 = of[j][1] * inv0;
        float v2 = of[j][2] * inv1, v3 = of[j][3] * inv1;
        *(uint32_t*)&ohi[row0 + d] = packbf(v0, v1);
        *(uint32_t*)&olo[row0 + d] = packbf(v0 - bfround(v0), v1 - bfround(v1));
        *(uint32_t*)&ohi[row1 + d] = packbf(v2, v3);
        *(uint32_t*)&olo[row1 + d] = packbf(v2 - bfround(v2), v3 - bfround(v3));
    }
}

// ---------------------------------------------------------------------------
extern "C" void kernel_launch(void* const* d_in, const int* in_sizes, int n_in,
                              void* d_out, int out_size)
{
    (void)in_sizes; (void)n_in; (void)out_size;
    const float* x      = (const float*)d_in[0];
    // d_in[1] = mask — strict-upper-triangular causal mask, applied analytically
    const float* W_attn = (const float*)d_in[2];
    const float* b_attn = (const float*)d_in[3];
    const float* W_proj = (const float*)d_in[4];
    const float* b_proj = (const float*)d_in[5];
    float* out = (float*)d_out;

    __nv_bfloat16 *qhi, *qlo, *xhi, *xlo, *wahi, *walo, *wphi, *wplo, *ahi, *alo;
    cudaGetSymbolAddress((void**)&qhi,  g_qkvhi);
    cudaGetSymbolAddress((void**)&qlo,  g_qkvlo);
    cudaGetSymbolAddress((void**)&xhi,  g_xhi);
    cudaGetSymbolAddress((void**)&xlo,  g_xlo);
    cudaGetSymbolAddress((void**)&wahi, g_wahi);
    cudaGetSymbolAddress((void**)&walo, g_walo);
    cudaGetSymbolAddress((void**)&wphi, g_wphi);
    cudaGetSymbolAddress((void**)&wplo, g_wplo);
    cudaGetSymbolAddress((void**)&ahi,  g_ahi);
    cudaGetSymbolAddress((void**)&alo,  g_alo);

    cudaFuncSetAttribute(gemm3_kernel,
                         cudaFuncAttributeMaxDynamicSharedMemorySize, G3_SMEM);
    cudaFuncSetAttribute(attn_hmma_kernel,
                         cudaFuncAttributeMaxDynamicSharedMemorySize, ATT_SMEM);

    {
        int n = MTOK * EE;
        convert_hilo_kernel<<<(n + 255) / 256, 256>>>(x, xhi, xlo, n);
        transpose_hilo_kernel<<<dim3(QKVN / 32, EE / 32), dim3(32, 8)>>>(
            W_attn, wahi, walo, EE, QKVN);
        transpose_hilo_kernel<<<dim3(EE / 32, EE / 32), dim3(32, 8)>>>(
            W_proj, wphi, wplo, EE, EE);
    }
    gemm3_kernel<<<dim3(QKVN / 128, MTOK / 128), 256, G3_SMEM>>>(
        xhi, xlo, wahi, walo, b_attn, nullptr, qhi, qlo, MTOK, QKVN, EE);
    attn_hmma_kernel<<<dim3(BB * NH, SS / 128), 256, ATT_SMEM>>>(qhi, qlo, ahi, alo);
    gemm3_kernel<<<dim3(EE / 128, MTOK / 128), 256, G3_SMEM>>>(
        ahi, alo, wphi, wplo, b_proj, out, nullptr, nullptr, MTOK, EE, EE);
}